// round 2
// baseline (speedup 1.0000x reference)
#include <cuda_runtime.h>
#include <math.h>

// Problem constants: B=2, L=2048, D=1024, H=16, hd=64
#define BB 2
#define LL 2048
#define DD 1024
#define NH 16
#define HD 64
#define ML (BB*LL)          // 4096 rows

// Scratch (global device arrays: allowed; no runtime allocation)
static __device__ float g_Q[ML*DD];
static __device__ float g_K[ML*DD];
static __device__ float g_V[ML*DD];
static __device__ float g_A[ML*DD];

// ---------------------------------------------------------------------------
// SGEMM: C[M,N] = A[M,K] @ W[N,K]^T   (both operands K-contiguous, row-major)
// 64x64x16 tiles, 256 threads, 4x4 microtile per thread.
// ---------------------------------------------------------------------------
__global__ __launch_bounds__(256) void sgemm_nt(
    const float* __restrict__ A, const float* __restrict__ W,
    float* __restrict__ C, int M, int N, int K)
{
    __shared__ float As[16][68];   // [k][row]
    __shared__ float Ws[16][68];   // [k][col]
    const int tid = threadIdx.x;
    const int tx = tid & 15, ty = tid >> 4;
    const int row0 = blockIdx.y * 64, col0 = blockIdx.x * 64;
    const int lr = tid >> 2;             // 0..63
    const int lc = (tid & 3) * 4;        // 0,4,8,12
    float acc[4][4] = {};

    for (int k0 = 0; k0 < K; k0 += 16) {
        float4 av = *(const float4*)&A[(size_t)(row0 + lr) * K + k0 + lc];
        float4 wv = *(const float4*)&W[(size_t)(col0 + lr) * K + k0 + lc];
        __syncthreads();
        As[lc+0][lr] = av.x; As[lc+1][lr] = av.y; As[lc+2][lr] = av.z; As[lc+3][lr] = av.w;
        Ws[lc+0][lr] = wv.x; Ws[lc+1][lr] = wv.y; Ws[lc+2][lr] = wv.z; Ws[lc+3][lr] = wv.w;
        __syncthreads();
        #pragma unroll
        for (int k = 0; k < 16; k++) {
            float4 a = *(const float4*)&As[k][ty*4];
            float4 b = *(const float4*)&Ws[k][tx*4];
            float ar[4] = {a.x, a.y, a.z, a.w};
            float br[4] = {b.x, b.y, b.z, b.w};
            #pragma unroll
            for (int i = 0; i < 4; i++)
                #pragma unroll
                for (int j = 0; j < 4; j++)
                    acc[i][j] += ar[i] * br[j];
        }
    }
    #pragma unroll
    for (int i = 0; i < 4; i++) {
        float4 o = {acc[i][0], acc[i][1], acc[i][2], acc[i][3]};
        *(float4*)&C[(size_t)(row0 + ty*4 + i) * N + col0 + tx*4] = o;
    }
}

// ---------------------------------------------------------------------------
// RoPE (in-place) on Q and K. Pair layout: within each head, (even,odd)
// adjacent elements rotate by freqs[pos][pair].
// ---------------------------------------------------------------------------
__global__ void rope_kernel(float* __restrict__ Q, float* __restrict__ Kk,
                            const float* __restrict__ freqs)
{
    int idx = blockIdx.x * blockDim.x + threadIdx.x;   // pair index
    if (idx >= ML * (DD/2)) return;
    int row = idx >> 9;          // / 512 pairs per row
    int p   = idx & 511;
    int l   = row & (LL - 1);
    int pp  = p & (HD/2 - 1);    // pair-within-head
    float fr = freqs[(l * (HD/2) + pp) * 2 + 0];
    float fi = freqs[(l * (HD/2) + pp) * 2 + 1];
    size_t base = (size_t)row * DD + p * 2;
    float2 q = *(float2*)&Q[base];
    float2 k = *(float2*)&Kk[base];
    float2 qo = {q.x*fr - q.y*fi, q.x*fi + q.y*fr};
    float2 ko = {k.x*fr - k.y*fi, k.x*fi + k.y*fr};
    *(float2*)&Q[base]  = qo;
    *(float2*)&Kk[base] = ko;
}

// ---------------------------------------------------------------------------
// Flash attention, causal. One block = one (b,h) x 64-row q tile.
// 256 threads, 4x4 microtiles for S and O. Online softmax, tiles with
// kv_start > q_end are skipped entirely; only the diagonal tile is masked.
// ---------------------------------------------------------------------------
#define FL_SMEM_FLOATS (4*64*68 + 192)

__global__ __launch_bounds__(256) void flash_attn(
    const float* __restrict__ Q, const float* __restrict__ K,
    const float* __restrict__ V, float* __restrict__ O)
{
    extern __shared__ float sm[];
    float* Qt  = sm;               // [dim 64][row 68]   (transposed)
    float* Kt  = Qt + 64*68;       // [dim 64][kv 68]    (transposed)
    float* Vs  = Kt + 64*68;       // [kv 64][dim 68]
    float* Ss  = Vs + 64*68;       // [q 64][kv 68]
    float* m_s = Ss + 64*68;
    float* l_s = m_s + 64;
    float* a_s = l_s + 64;

    const int tid = threadIdx.x;
    const int tx = tid & 15, ty = tid >> 4;
    const int b = blockIdx.y >> 4, h = blockIdx.y & 15;
    const int q0 = blockIdx.x * 64;
    const size_t headoff = (size_t)b * LL * DD + (size_t)h * HD;

    // load Q tile transposed
    for (int e = tid; e < 1024; e += 256) {
        int r = e >> 4, c = (e & 15) * 4;
        float4 qv = *(const float4*)&Q[headoff + (size_t)(q0 + r) * DD + c];
        Qt[(c+0)*68 + r] = qv.x; Qt[(c+1)*68 + r] = qv.y;
        Qt[(c+2)*68 + r] = qv.z; Qt[(c+3)*68 + r] = qv.w;
    }
    if (tid < 64) { m_s[tid] = -1e30f; l_s[tid] = 0.f; }

    float acc[4][4] = {};
    const int ntiles = blockIdx.x + 1;

    for (int kt = 0; kt < ntiles; kt++) {
        const int kv0 = kt * 64;
        __syncthreads();   // protect Kt/Vs/Ss from previous iteration readers
        for (int e = tid; e < 1024; e += 256) {
            int r = e >> 4, c = (e & 15) * 4;
            float4 kv = *(const float4*)&K[headoff + (size_t)(kv0 + r) * DD + c];
            float4 vv = *(const float4*)&V[headoff + (size_t)(kv0 + r) * DD + c];
            Kt[(c+0)*68 + r] = kv.x; Kt[(c+1)*68 + r] = kv.y;
            Kt[(c+2)*68 + r] = kv.z; Kt[(c+3)*68 + r] = kv.w;
            *(float4*)&Vs[r*68 + c] = vv;
        }
        __syncthreads();

        // S = Q @ K^T  (4x4 per thread)
        float s[4][4] = {};
        #pragma unroll 8
        for (int k = 0; k < 64; k++) {
            float4 a = *(const float4*)&Qt[k*68 + ty*4];
            float4 bq = *(const float4*)&Kt[k*68 + tx*4];
            float ar[4] = {a.x, a.y, a.z, a.w};
            float br[4] = {bq.x, bq.y, bq.z, bq.w};
            #pragma unroll
            for (int i = 0; i < 4; i++)
                #pragma unroll
                for (int j = 0; j < 4; j++)
                    s[i][j] += ar[i] * br[j];
        }
        const bool diag = (kt == ntiles - 1);
        #pragma unroll
        for (int i = 0; i < 4; i++) {
            int gr = q0 + ty*4 + i;
            #pragma unroll
            for (int j = 0; j < 4; j++) {
                int gc = kv0 + tx*4 + j;
                float v = s[i][j] * 0.125f;   // 1/sqrt(64)
                if (diag && gc > gr) v = -1e30f;
                s[i][j] = v;
            }
            float4 o = {s[i][0], s[i][1], s[i][2], s[i][3]};
            *(float4*)&Ss[(ty*4 + i)*68 + tx*4] = o;
        }
        __syncthreads();

        // online softmax: one thread per q row
        if (tid < 64) {
            const int r = tid;
            float mold = m_s[r];
            float mx = mold;
            #pragma unroll 8
            for (int c = 0; c < 64; c++) mx = fmaxf(mx, Ss[r*68 + c]);
            float alpha = __expf(mold - mx);
            float sum = 0.f;
            #pragma unroll 8
            for (int c = 0; c < 64; c++) {
                float p = __expf(Ss[r*68 + c] - mx);
                Ss[r*68 + c] = p;
                sum += p;
            }
            l_s[r] = l_s[r] * alpha + sum;
            m_s[r] = mx;
            a_s[r] = alpha;
        }
        __syncthreads();

        // O = O*alpha + P @ V
        float al[4];
        #pragma unroll
        for (int i = 0; i < 4; i++) al[i] = a_s[ty*4 + i];
        #pragma unroll
        for (int i = 0; i < 4; i++)
            #pragma unroll
            for (int j = 0; j < 4; j++)
                acc[i][j] *= al[i];
        #pragma unroll 8
        for (int k = 0; k < 64; k++) {
            float4 vv = *(const float4*)&Vs[k*68 + tx*4];
            float vr[4] = {vv.x, vv.y, vv.z, vv.w};
            float pr[4];
            #pragma unroll
            for (int i = 0; i < 4; i++) pr[i] = Ss[(ty*4 + i)*68 + k];
            #pragma unroll
            for (int i = 0; i < 4; i++)
                #pragma unroll
                for (int j = 0; j < 4; j++)
                    acc[i][j] += pr[i] * vr[j];
        }
    }

    // finalize and write (attn output back in [b, l, h*64+d] layout)
    #pragma unroll
    for (int i = 0; i < 4; i++) {
        float inv = 1.f / l_s[ty*4 + i];
        float4 o = {acc[i][0]*inv, acc[i][1]*inv, acc[i][2]*inv, acc[i][3]*inv};
        *(float4*)&O[headoff + (size_t)(q0 + ty*4 + i) * DD + tx*4] = o;
    }
}

// ---------------------------------------------------------------------------
extern "C" void kernel_launch(void* const* d_in, const int* in_sizes, int n_in,
                              void* d_out, int out_size)
{
    const float* x     = (const float*)d_in[0];
    const float* freqs = (const float*)d_in[1];
    // d_in[2] = attention_mask (pure causal; implemented structurally)
    const float* Wq = (const float*)d_in[3];
    const float* Wk = (const float*)d_in[4];
    const float* Wv = (const float*)d_in[5];
    const float* Wo = (const float*)d_in[6];
    float* out = (float*)d_out;

    float *pQ, *pK, *pV, *pA;
    cudaGetSymbolAddress((void**)&pQ, g_Q);
    cudaGetSymbolAddress((void**)&pK, g_K);
    cudaGetSymbolAddress((void**)&pV, g_V);
    cudaGetSymbolAddress((void**)&pA, g_A);

    dim3 gg(DD/64, ML/64);   // (16, 64)
    sgemm_nt<<<gg, 256>>>(x, Wq, pQ, ML, DD, DD);
    sgemm_nt<<<gg, 256>>>(x, Wk, pK, ML, DD, DD);
    sgemm_nt<<<gg, 256>>>(x, Wv, pV, ML, DD, DD);

    rope_kernel<<<(ML*(DD/2) + 255)/256, 256>>>(pQ, pK, freqs);

    const int fsm = FL_SMEM_FLOATS * (int)sizeof(float);   // ~70.4 KB
    cudaFuncSetAttribute(flash_attn, cudaFuncAttributeMaxDynamicSharedMemorySize, fsm);
    flash_attn<<<dim3(LL/64, BB*NH), 256, fsm>>>(pQ, pK, pV, pA);

    sgemm_nt<<<gg, 256>>>(pA, Wo, out, ML, DD, DD);
}

// round 3
// speedup vs baseline: 1.9993x; 1.9993x over previous
#include <cuda_runtime.h>

// Problem constants: B=2, L=2048, D=1024, H=16, hd=64
#define BB 2
#define LL 2048
#define DD 1024
#define NH 16
#define HD 64
#define ML (BB*LL)          // 4096 rows

static __device__ float g_Q[ML*DD];
static __device__ float g_K[ML*DD];
static __device__ float g_V[ML*DD];
static __device__ float g_A[ML*DD];

__device__ __forceinline__ unsigned f2tf(float f) {
    unsigned u; asm("cvt.rna.tf32.f32 %0, %1;" : "=r"(u) : "f"(f)); return u;
}

__device__ __forceinline__ void mma8(float* c, const unsigned* a, const unsigned* b) {
    asm volatile("mma.sync.aligned.m16n8k8.row.col.f32.tf32.tf32.f32 "
        "{%0,%1,%2,%3}, {%4,%5,%6,%7}, {%8,%9}, {%0,%1,%2,%3};"
        : "+f"(c[0]), "+f"(c[1]), "+f"(c[2]), "+f"(c[3])
        : "r"(a[0]), "r"(a[1]), "r"(a[2]), "r"(a[3]), "r"(b[0]), "r"(b[1]));
}

// ---------------------------------------------------------------------------
// TF32 GEMM: C[M,N] = A[M,K] @ W[N,K]^T. 128x128x16 tiles, 256 thr (8 warps),
// warp tile 32x64 (2 m16 x 8 n8). Smem [k][m]/[k][n] pad 136 -> conflict-free
// fragment loads (bank = 8t+g) and rotated conflict-free scatter stores.
// grid.z selects among up to 3 (W, C) pairs for fused QKV.
// ---------------------------------------------------------------------------
#define GBK 16
#define GLD 136

__global__ __launch_bounds__(256) void gemm_tf32(
    const float* __restrict__ A,
    const float* __restrict__ W0, const float* __restrict__ W1, const float* __restrict__ W2,
    float* __restrict__ C0, float* __restrict__ C1, float* __restrict__ C2,
    int M, int N, int K)
{
    const float* W = (blockIdx.z == 0) ? W0 : (blockIdx.z == 1) ? W1 : W2;
    float*       C = (blockIdx.z == 0) ? C0 : (blockIdx.z == 1) ? C1 : C2;

    __shared__ unsigned As[GBK][GLD];
    __shared__ unsigned Bs[GBK][GLD];
    const int tid  = threadIdx.x;
    const int lane = tid & 31;
    const int warp = tid >> 5;
    const int g = lane >> 2, t = lane & 3;
    const int wm = (warp & 3) * 32;
    const int wn = (warp >> 2) * 64;
    const int row0 = blockIdx.y * 128, col0 = blockIdx.x * 128;

    const int lr = tid >> 2;        // 0..63
    const int tt = tid & 3;
    const int lk = tt * 4;          // 0,4,8,12

    float c[2][8][4] = {};

    const float* Ap = A + (size_t)(row0 + lr) * K + lk;
    const float* Wp = W + (size_t)(col0 + lr) * K + lk;

    for (int k0 = 0; k0 < K; k0 += GBK) {
        float4 a0 = *(const float4*)(Ap + k0);
        float4 a1 = *(const float4*)(Ap + k0 + (size_t)64 * K);
        float4 b0 = *(const float4*)(Wp + k0);
        float4 b1 = *(const float4*)(Wp + k0 + (size_t)64 * K);
        float av0[4] = {a0.x, a0.y, a0.z, a0.w};
        float av1[4] = {a1.x, a1.y, a1.z, a1.w};
        float bv0[4] = {b0.x, b0.y, b0.z, b0.w};
        float bv1[4] = {b1.x, b1.y, b1.z, b1.w};
        __syncthreads();
        #pragma unroll
        for (int s = 0; s < 4; s++) {
            int j = (s + tt) & 3;   // rotate -> conflict-free STS
            As[lk + j][lr]      = f2tf(av0[j]);
            As[lk + j][lr + 64] = f2tf(av1[j]);
            Bs[lk + j][lr]      = f2tf(bv0[j]);
            Bs[lk + j][lr + 64] = f2tf(bv1[j]);
        }
        __syncthreads();
        #pragma unroll
        for (int kk = 0; kk < GBK; kk += 8) {
            unsigned af[2][4], bf[8][2];
            #pragma unroll
            for (int mi = 0; mi < 2; mi++) {
                int m = wm + mi * 16 + g;
                af[mi][0] = As[kk + t][m];
                af[mi][1] = As[kk + t][m + 8];
                af[mi][2] = As[kk + t + 4][m];
                af[mi][3] = As[kk + t + 4][m + 8];
            }
            #pragma unroll
            for (int ni = 0; ni < 8; ni++) {
                int n = wn + ni * 8 + g;
                bf[ni][0] = Bs[kk + t][n];
                bf[ni][1] = Bs[kk + t + 4][n];
            }
            #pragma unroll
            for (int mi = 0; mi < 2; mi++)
                #pragma unroll
                for (int ni = 0; ni < 8; ni++)
                    mma8(c[mi][ni], af[mi], bf[ni]);
        }
    }
    #pragma unroll
    for (int mi = 0; mi < 2; mi++) {
        int r = row0 + wm + mi * 16 + g;
        #pragma unroll
        for (int ni = 0; ni < 8; ni++) {
            int cc = col0 + wn + ni * 8 + t * 2;
            *(float2*)&C[(size_t)r * N + cc]       = make_float2(c[mi][ni][0], c[mi][ni][1]);
            *(float2*)&C[(size_t)(r + 8) * N + cc] = make_float2(c[mi][ni][2], c[mi][ni][3]);
        }
    }
}

// ---------------------------------------------------------------------------
// RoPE (in-place) on Q and K.
// ---------------------------------------------------------------------------
__global__ void rope_kernel(float* __restrict__ Q, float* __restrict__ Kk,
                            const float* __restrict__ freqs)
{
    int idx = blockIdx.x * blockDim.x + threadIdx.x;   // pair index
    if (idx >= ML * (DD/2)) return;
    int row = idx >> 9;
    int p   = idx & 511;
    int l   = row & (LL - 1);
    int pp  = p & (HD/2 - 1);
    float fr = freqs[(l * (HD/2) + pp) * 2 + 0];
    float fi = freqs[(l * (HD/2) + pp) * 2 + 1];
    size_t base = (size_t)row * DD + p * 2;
    float2 q = *(float2*)&Q[base];
    float2 k = *(float2*)&Kk[base];
    *(float2*)&Q[base]  = make_float2(q.x*fr - q.y*fi, q.x*fi + q.y*fr);
    *(float2*)&Kk[base] = make_float2(k.x*fr - k.y*fi, k.x*fi + k.y*fr);
}

// ---------------------------------------------------------------------------
// Flash attention (causal) on tensor pipe. Block = (b,h) x 64 q rows.
// 8 warps, each owns a 16x32 slab of the 64x64 S / O tiles.
// Q/K row-major [r][68] tf32, V [kv][72] tf32, Ss [q][68] fp32 then tf32 P.
// ---------------------------------------------------------------------------
#define FLD 68
#define VLD 72
#define FL_SMEM_WORDS (3*64*FLD + 64*VLD + 192)

__global__ __launch_bounds__(256) void flash_tf32(
    const float* __restrict__ Q, const float* __restrict__ K,
    const float* __restrict__ V, float* __restrict__ O)
{
    extern __shared__ unsigned sm[];
    unsigned* Qs = sm;                      // [64][FLD]
    unsigned* Ks = Qs + 64*FLD;             // [64][FLD]
    unsigned* Vs = Ks + 64*FLD;             // [64][VLD]
    float*    Ss = (float*)(Vs + 64*VLD);   // [64][FLD]
    float* m_s = Ss + 64*FLD;
    float* l_s = m_s + 64;
    float* a_s = l_s + 64;

    const int tid = threadIdx.x;
    const int lane = tid & 31, warp = tid >> 5;
    const int g = lane >> 2, t = lane & 3;
    const int wr = (warp & 3) * 16;     // warp's q-row block
    const int wc = (warp >> 2) * 32;    // warp's col block (kv for S, hd for O)
    const int b = blockIdx.y >> 4, h = blockIdx.y & 15;
    const int q0 = blockIdx.x * 64;
    const size_t headoff = (size_t)b * LL * DD + (size_t)h * HD;

    // Load Q tile (tf32)
    for (int e = tid; e < 64*16; e += 256) {
        int r = e >> 4, ci = (e & 15) * 4;
        float4 qv = *(const float4*)&Q[headoff + (size_t)(q0 + r) * DD + ci];
        unsigned* p = &Qs[r*FLD + ci];
        p[0] = f2tf(qv.x); p[1] = f2tf(qv.y); p[2] = f2tf(qv.z); p[3] = f2tf(qv.w);
    }
    if (tid < 64) { m_s[tid] = -1e30f; l_s[tid] = 0.f; }

    float acc[4][4] = {};
    const int ntiles = blockIdx.x + 1;

    for (int kt = 0; kt < ntiles; kt++) {
        const int kv0 = kt * 64;
        __syncthreads();
        for (int e = tid; e < 64*16; e += 256) {
            int r = e >> 4, ci = (e & 15) * 4;
            float4 kv = *(const float4*)&K[headoff + (size_t)(kv0 + r) * DD + ci];
            float4 vv = *(const float4*)&V[headoff + (size_t)(kv0 + r) * DD + ci];
            unsigned* pk = &Ks[r*FLD + ci];
            pk[0] = f2tf(kv.x); pk[1] = f2tf(kv.y); pk[2] = f2tf(kv.z); pk[3] = f2tf(kv.w);
            unsigned* pv = &Vs[r*VLD + ci];
            pv[0] = f2tf(vv.x); pv[1] = f2tf(vv.y); pv[2] = f2tf(vv.z); pv[3] = f2tf(vv.w);
        }
        __syncthreads();

        // S = Q @ K^T
        float sfrag[4][4] = {};
        #pragma unroll
        for (int kk = 0; kk < HD; kk += 8) {
            unsigned af[4], bf[2];
            int m = wr + g;
            af[0] = Qs[m*FLD + kk + t];
            af[1] = Qs[(m+8)*FLD + kk + t];
            af[2] = Qs[m*FLD + kk + t + 4];
            af[3] = Qs[(m+8)*FLD + kk + t + 4];
            #pragma unroll
            for (int ni = 0; ni < 4; ni++) {
                int n = wc + ni*8 + g;
                bf[0] = Ks[n*FLD + kk + t];
                bf[1] = Ks[n*FLD + kk + t + 4];
                mma8(sfrag[ni], af, bf);
            }
        }
        // scale + causal mask + store S
        const bool diag = (kt == ntiles - 1);
        #pragma unroll
        for (int ni = 0; ni < 4; ni++) {
            int r0r = wr + g, r1 = r0r + 8;
            int cc = wc + ni*8 + t*2;
            float v0 = sfrag[ni][0]*0.125f, v1 = sfrag[ni][1]*0.125f;
            float v2 = sfrag[ni][2]*0.125f, v3 = sfrag[ni][3]*0.125f;
            if (diag) {
                int gr0 = q0 + r0r, gr1 = q0 + r1, gc = kv0 + cc;
                if (gc     > gr0) v0 = -1e30f;
                if (gc + 1 > gr0) v1 = -1e30f;
                if (gc     > gr1) v2 = -1e30f;
                if (gc + 1 > gr1) v3 = -1e30f;
            }
            *(float2*)&Ss[r0r*FLD + cc] = make_float2(v0, v1);
            *(float2*)&Ss[r1*FLD + cc]  = make_float2(v2, v3);
        }
        __syncthreads();

        // Online softmax: 4 threads per row, shfl reductions. Writes P as tf32.
        {
            int r = tid >> 2, c4o = tid & 3;
            float mold = m_s[r];
            float mx = mold;
            #pragma unroll
            for (int c4 = 0; c4 < 16; c4++) mx = fmaxf(mx, Ss[r*FLD + c4*4 + c4o]);
            mx = fmaxf(mx, __shfl_xor_sync(0xffffffffu, mx, 1));
            mx = fmaxf(mx, __shfl_xor_sync(0xffffffffu, mx, 2));
            float sum = 0.f;
            #pragma unroll
            for (int c4 = 0; c4 < 16; c4++) {
                int idx = r*FLD + c4*4 + c4o;
                float p = __expf(Ss[idx] - mx);
                sum += p;
                ((unsigned*)Ss)[idx] = f2tf(p);
            }
            sum += __shfl_xor_sync(0xffffffffu, sum, 1);
            sum += __shfl_xor_sync(0xffffffffu, sum, 2);
            if (c4o == 0) {
                float alpha = __expf(mold - mx);
                l_s[r] = l_s[r] * alpha + sum;
                m_s[r] = mx;
                a_s[r] = alpha;
            }
        }
        __syncthreads();

        // Rescale O accumulator, then O += P @ V
        {
            float al0 = a_s[wr + g], al1 = a_s[wr + g + 8];
            #pragma unroll
            for (int ni = 0; ni < 4; ni++) {
                acc[ni][0] *= al0; acc[ni][1] *= al0;
                acc[ni][2] *= al1; acc[ni][3] *= al1;
            }
        }
        const unsigned* Pu = (const unsigned*)Ss;
        #pragma unroll
        for (int kk = 0; kk < 64; kk += 8) {
            unsigned af[4], bf[2];
            int m = wr + g;
            af[0] = Pu[m*FLD + kk + t];
            af[1] = Pu[(m+8)*FLD + kk + t];
            af[2] = Pu[m*FLD + kk + t + 4];
            af[3] = Pu[(m+8)*FLD + kk + t + 4];
            #pragma unroll
            for (int ni = 0; ni < 4; ni++) {
                int n = wc + ni*8 + g;
                bf[0] = Vs[(kk + t)*VLD + n];
                bf[1] = Vs[(kk + t + 4)*VLD + n];
                mma8(acc[ni], af, bf);
            }
        }
    }

    // Epilogue: divide by l, store
    {
        int r0r = wr + g, r1 = r0r + 8;
        float inv0 = 1.f / l_s[r0r], inv1 = 1.f / l_s[r1];
        #pragma unroll
        for (int ni = 0; ni < 4; ni++) {
            int cc = wc + ni*8 + t*2;
            *(float2*)&O[headoff + (size_t)(q0 + r0r)*DD + cc] =
                make_float2(acc[ni][0]*inv0, acc[ni][1]*inv0);
            *(float2*)&O[headoff + (size_t)(q0 + r1)*DD + cc] =
                make_float2(acc[ni][2]*inv1, acc[ni][3]*inv1);
        }
    }
}

// ---------------------------------------------------------------------------
extern "C" void kernel_launch(void* const* d_in, const int* in_sizes, int n_in,
                              void* d_out, int out_size)
{
    const float* x     = (const float*)d_in[0];
    const float* freqs = (const float*)d_in[1];
    // d_in[2] = attention_mask (pure causal; handled structurally)
    const float* Wq = (const float*)d_in[3];
    const float* Wk = (const float*)d_in[4];
    const float* Wv = (const float*)d_in[5];
    const float* Wo = (const float*)d_in[6];
    float* out = (float*)d_out;

    float *pQ, *pK, *pV, *pA;
    cudaGetSymbolAddress((void**)&pQ, g_Q);
    cudaGetSymbolAddress((void**)&pK, g_K);
    cudaGetSymbolAddress((void**)&pV, g_V);
    cudaGetSymbolAddress((void**)&pA, g_A);

    // Fused QKV projections (grid.z = 3)
    gemm_tf32<<<dim3(DD/128, ML/128, 3), 256>>>(x, Wq, Wk, Wv, pQ, pK, pV, ML, DD, DD);

    rope_kernel<<<(ML*(DD/2) + 255)/256, 256>>>(pQ, pK, freqs);

    const int fsm = FL_SMEM_WORDS * (int)sizeof(unsigned);   // ~71.5 KB
    cudaFuncSetAttribute(flash_tf32, cudaFuncAttributeMaxDynamicSharedMemorySize, fsm);
    flash_tf32<<<dim3(LL/64, BB*NH), 256, fsm>>>(pQ, pK, pV, pA);

    // Output projection
    gemm_tf32<<<dim3(DD/128, ML/128, 1), 256>>>(pA, Wo, Wo, Wo, out, out, out, ML, DD, DD);
}

// round 5
// speedup vs baseline: 4.0120x; 2.0066x over previous
#include <cuda_runtime.h>
#include <cuda_fp16.h>
#include <cstdint>

// Problem constants: B=2, L=2048, D=1024, H=16, hd=64
#define BB 2
#define LL 2048
#define DD 1024
#define NH 16
#define HD 64
#define ML (BB*LL)          // 4096 rows

static __device__ float g_Q[ML*DD];
static __device__ float g_K[ML*DD];
static __device__ float g_V[ML*DD];
static __device__ float g_A[ML*DD];

// ---------------------------------------------------------------------------
// helpers
// ---------------------------------------------------------------------------
__device__ __forceinline__ uint32_t smem_u32(const void* p) {
    uint32_t a;
    asm("{ .reg .u64 t; cvta.to.shared.u64 t, %1; cvt.u32.u64 %0, t; }" : "=r"(a) : "l"(p));
    return a;
}

__device__ __forceinline__ uint32_t f2h2(float x, float y) {
    __half2 h = __floats2half2_rn(x, y);
    return *(uint32_t*)&h;
}

#define LDSM4(r0,r1,r2,r3, addr) \
    asm volatile("ldmatrix.sync.aligned.m8n8.x4.shared.b16 {%0,%1,%2,%3}, [%4];" \
        : "=r"(r0),"=r"(r1),"=r"(r2),"=r"(r3) : "r"(addr))

#define LDSM4T(r0,r1,r2,r3, addr) \
    asm volatile("ldmatrix.sync.aligned.m8n8.x4.trans.shared.b16 {%0,%1,%2,%3}, [%4];" \
        : "=r"(r0),"=r"(r1),"=r"(r2),"=r"(r3) : "r"(addr))

// m16n8k16 fp16 -> fp32
__device__ __forceinline__ void mma16(float* c, const uint32_t* a, uint32_t b0, uint32_t b1) {
    asm volatile("mma.sync.aligned.m16n8k16.row.col.f32.f16.f16.f32 "
        "{%0,%1,%2,%3}, {%4,%5,%6,%7}, {%8,%9}, {%0,%1,%2,%3};"
        : "+f"(c[0]), "+f"(c[1]), "+f"(c[2]), "+f"(c[3])
        : "r"(a[0]), "r"(a[1]), "r"(a[2]), "r"(a[3]), "r"(b0), "r"(b1));
}

// ---------------------------------------------------------------------------
// FP16 GEMM: C[M,N] = A[M,K] @ W[N,K]^T.  128x128x32 tiles, 256 thr (8 warps),
// warp tile 32x64.  A/B smem [row][40] halves (80B stride -> conflict-free
// ldmatrix).  Fragments via ldmatrix.x4 non-trans for both A and B.
// grid.z selects (W,C) pair for fused QKV.
// ---------------------------------------------------------------------------
#define BM 128
#define BN 128
#define BK 32
#define ALD 40    // halves per smem row

__global__ __launch_bounds__(256) void gemm_f16(
    const float* __restrict__ A,
    const float* __restrict__ W0, const float* __restrict__ W1, const float* __restrict__ W2,
    float* __restrict__ C0, float* __restrict__ C1, float* __restrict__ C2)
{
    const float* W = (blockIdx.z == 0) ? W0 : (blockIdx.z == 1) ? W1 : W2;
    float*       C = (blockIdx.z == 0) ? C0 : (blockIdx.z == 1) ? C1 : C2;

    __shared__ __half As[BM][ALD];
    __shared__ __half Bs[BN][ALD];

    const int tid  = threadIdx.x;
    const int lane = tid & 31, warp = tid >> 5;
    const int g = lane >> 2, t = lane & 3;
    const int lrow = lane & 15, lko = (lane >> 4) * 8;
    const int wm = (warp & 3) * 32;
    const int wn = (warp >> 2) * 64;
    const int row0 = blockIdx.y * BM, col0 = blockIdx.x * BN;

    const uint32_t asm_ = smem_u32(&As[0][0]);
    const uint32_t bsm_ = smem_u32(&Bs[0][0]);

    // load assignment: 512 16B-chunks per tile; thread -> chunks tid, tid+256
    const int rA = tid >> 2;            // 0..63
    const int c8 = (tid & 3) * 8;       // half offset in row

    const float* Ap = A + (size_t)(row0 + rA) * DD + c8;
    const float* Wp = W + (size_t)(col0 + rA) * DD + c8;

    float c[2][8][4] = {};

    for (int k0 = 0; k0 < DD; k0 += BK) {
        float4 a00 = *(const float4*)(Ap + k0);
        float4 a01 = *(const float4*)(Ap + k0 + 4);
        float4 a10 = *(const float4*)(Ap + k0 + (size_t)64 * DD);
        float4 a11 = *(const float4*)(Ap + k0 + (size_t)64 * DD + 4);
        float4 b00 = *(const float4*)(Wp + k0);
        float4 b01 = *(const float4*)(Wp + k0 + 4);
        float4 b10 = *(const float4*)(Wp + k0 + (size_t)64 * DD);
        float4 b11 = *(const float4*)(Wp + k0 + (size_t)64 * DD + 4);
        __syncthreads();
        {
            uint32_t o0 = (uint32_t)(rA * ALD + c8) * 2;
            uint32_t o1 = (uint32_t)((rA + 64) * ALD + c8) * 2;
            asm volatile("st.shared.v4.b32 [%0], {%1,%2,%3,%4};" :: "r"(asm_ + o0),
                "r"(f2h2(a00.x,a00.y)), "r"(f2h2(a00.z,a00.w)),
                "r"(f2h2(a01.x,a01.y)), "r"(f2h2(a01.z,a01.w)));
            asm volatile("st.shared.v4.b32 [%0], {%1,%2,%3,%4};" :: "r"(asm_ + o1),
                "r"(f2h2(a10.x,a10.y)), "r"(f2h2(a10.z,a10.w)),
                "r"(f2h2(a11.x,a11.y)), "r"(f2h2(a11.z,a11.w)));
            asm volatile("st.shared.v4.b32 [%0], {%1,%2,%3,%4};" :: "r"(bsm_ + o0),
                "r"(f2h2(b00.x,b00.y)), "r"(f2h2(b00.z,b00.w)),
                "r"(f2h2(b01.x,b01.y)), "r"(f2h2(b01.z,b01.w)));
            asm volatile("st.shared.v4.b32 [%0], {%1,%2,%3,%4};" :: "r"(bsm_ + o1),
                "r"(f2h2(b10.x,b10.y)), "r"(f2h2(b10.z,b10.w)),
                "r"(f2h2(b11.x,b11.y)), "r"(f2h2(b11.z,b11.w)));
        }
        __syncthreads();

        #pragma unroll
        for (int ks = 0; ks < 2; ks++) {
            const int kk = ks * 16;
            uint32_t af[2][4];
            #pragma unroll
            for (int mi = 0; mi < 2; mi++) {
                uint32_t ad = asm_ + (uint32_t)((wm + mi*16 + lrow) * ALD + kk + lko) * 2;
                LDSM4(af[mi][0], af[mi][1], af[mi][2], af[mi][3], ad);
            }
            #pragma unroll
            for (int n2 = 0; n2 < 4; n2++) {
                uint32_t r0, r1, r2, r3;
                uint32_t bd = bsm_ + (uint32_t)((wn + n2*16 + lrow) * ALD + kk + lko) * 2;
                LDSM4(r0, r1, r2, r3, bd);
                #pragma unroll
                for (int mi = 0; mi < 2; mi++) {
                    mma16(c[mi][n2*2],   af[mi], r0, r2);   // n = wn + n2*16 + 0..7
                    mma16(c[mi][n2*2+1], af[mi], r1, r3);   // n = wn + n2*16 + 8..15
                }
            }
        }
    }
    #pragma unroll
    for (int mi = 0; mi < 2; mi++) {
        int r = row0 + wm + mi * 16 + g;
        #pragma unroll
        for (int ni = 0; ni < 8; ni++) {
            int cc = col0 + wn + (ni >> 1) * 16 + (ni & 1) * 8 + t * 2;
            *(float2*)&C[(size_t)r * DD + cc]       = make_float2(c[mi][ni][0], c[mi][ni][1]);
            *(float2*)&C[(size_t)(r + 8) * DD + cc] = make_float2(c[mi][ni][2], c[mi][ni][3]);
        }
    }
}

// ---------------------------------------------------------------------------
// RoPE (in-place) on Q and K.
// ---------------------------------------------------------------------------
__global__ void rope_kernel(float* __restrict__ Q, float* __restrict__ Kk,
                            const float* __restrict__ freqs)
{
    int idx = blockIdx.x * blockDim.x + threadIdx.x;
    if (idx >= ML * (DD/2)) return;
    int row = idx >> 9;
    int p   = idx & 511;
    int l   = row & (LL - 1);
    int pp  = p & (HD/2 - 1);
    float fr = freqs[(l * (HD/2) + pp) * 2 + 0];
    float fi = freqs[(l * (HD/2) + pp) * 2 + 1];
    size_t base = (size_t)row * DD + p * 2;
    float2 q = *(float2*)&Q[base];
    float2 k = *(float2*)&Kk[base];
    *(float2*)&Q[base]  = make_float2(q.x*fr - q.y*fi, q.x*fi + q.y*fr);
    *(float2*)&Kk[base] = make_float2(k.x*fr - k.y*fi, k.x*fi + k.y*fr);
}

// ---------------------------------------------------------------------------
// Flash attention (causal), fp16 MMA + ldmatrix. Block = (b,h) x 64 q rows.
// 8 warps: wr=(warp&3)*16 q-rows, wc=(warp>>2)*32 cols (kv for S, hd for O).
// Qs/Ks/Vs/Ps: [64][72] halves (144B stride).  Ss: [64][68] fp32.
// ---------------------------------------------------------------------------
#define HLD 72
#define SLD 68
#define FL_SMEM_BYTES (4*64*HLD*2 + 64*SLD*4 + 3*64*4)

__global__ __launch_bounds__(256) void flash_f16(
    const float* __restrict__ Q, const float* __restrict__ K,
    const float* __restrict__ V, float* __restrict__ O)
{
    extern __shared__ __half hsm[];
    __half* Qs = hsm;                 // [64][HLD]
    __half* Ks = Qs + 64*HLD;
    __half* Vs = Ks + 64*HLD;         // [kv][hd] row-major (trans-ldsm)
    __half* Ps = Vs + 64*HLD;
    float*  Ss = (float*)(Ps + 64*HLD);  // [64][SLD]
    float* m_s = Ss + 64*SLD;
    float* l_s = m_s + 64;
    float* a_s = l_s + 64;

    const int tid = threadIdx.x;
    const int lane = tid & 31, warp = tid >> 5;
    const int g = lane >> 2, t = lane & 3;
    const int lrow = lane & 15, lko = (lane >> 4) * 8;
    const int wr = (warp & 3) * 16;
    const int wc = (warp >> 2) * 32;
    const int b = blockIdx.y >> 4, h = blockIdx.y & 15;
    const int q0 = blockIdx.x * 64;
    const size_t headoff = (size_t)b * LL * DD + (size_t)h * HD;

    const uint32_t qsm = smem_u32(Qs), ksm = smem_u32(Ks),
                   vsm = smem_u32(Vs), psm = smem_u32(Ps);

    for (int e = tid; e < 64*16; e += 256) {
        int r = e >> 4, ci = (e & 15) * 4;
        float4 qv = *(const float4*)&Q[headoff + (size_t)(q0 + r) * DD + ci];
        *(__half2*)&Qs[r*HLD + ci]     = __floats2half2_rn(qv.x, qv.y);
        *(__half2*)&Qs[r*HLD + ci + 2] = __floats2half2_rn(qv.z, qv.w);
    }
    if (tid < 64) { m_s[tid] = -1e30f; l_s[tid] = 0.f; }

    float acc[4][4] = {};
    const int ntiles = blockIdx.x + 1;

    for (int kt = 0; kt < ntiles; kt++) {
        const int kv0 = kt * 64;
        __syncthreads();
        for (int e = tid; e < 64*16; e += 256) {
            int r = e >> 4, ci = (e & 15) * 4;
            float4 kv = *(const float4*)&K[headoff + (size_t)(kv0 + r) * DD + ci];
            float4 vv = *(const float4*)&V[headoff + (size_t)(kv0 + r) * DD + ci];
            *(__half2*)&Ks[r*HLD + ci]     = __floats2half2_rn(kv.x, kv.y);
            *(__half2*)&Ks[r*HLD + ci + 2] = __floats2half2_rn(kv.z, kv.w);
            *(__half2*)&Vs[r*HLD + ci]     = __floats2half2_rn(vv.x, vv.y);
            *(__half2*)&Vs[r*HLD + ci + 2] = __floats2half2_rn(vv.z, vv.w);
        }
        __syncthreads();

        // S = Q @ K^T  (warp: 16 x 32)
        float sfrag[4][4] = {};
        #pragma unroll
        for (int kk = 0; kk < HD; kk += 16) {
            uint32_t af[4];
            LDSM4(af[0], af[1], af[2], af[3],
                  qsm + (uint32_t)((wr + lrow) * HLD + kk + lko) * 2);
            #pragma unroll
            for (int n2 = 0; n2 < 2; n2++) {
                uint32_t r0, r1, r2, r3;
                LDSM4(r0, r1, r2, r3,
                      ksm + (uint32_t)((wc + n2*16 + lrow) * HLD + kk + lko) * 2);
                mma16(sfrag[n2*2],   af, r0, r2);
                mma16(sfrag[n2*2+1], af, r1, r3);
            }
        }
        const bool diag = (kt == ntiles - 1);
        #pragma unroll
        for (int ni = 0; ni < 4; ni++) {
            int r0r = wr + g, r1 = r0r + 8;
            int cc = wc + (ni >> 1) * 16 + (ni & 1) * 8 + t * 2;
            float v0 = sfrag[ni][0]*0.125f, v1 = sfrag[ni][1]*0.125f;
            float v2 = sfrag[ni][2]*0.125f, v3 = sfrag[ni][3]*0.125f;
            if (diag) {
                int gr0 = q0 + r0r, gr1 = q0 + r1, gc = kv0 + cc;
                if (gc     > gr0) v0 = -1e30f;
                if (gc + 1 > gr0) v1 = -1e30f;
                if (gc     > gr1) v2 = -1e30f;
                if (gc + 1 > gr1) v3 = -1e30f;
            }
            *(float2*)&Ss[r0r*SLD + cc] = make_float2(v0, v1);
            *(float2*)&Ss[r1*SLD + cc]  = make_float2(v2, v3);
        }
        __syncthreads();

        // online softmax: 4 threads per row; writes P as fp16
        {
            int r = tid >> 2, c4o = tid & 3;
            float mold = m_s[r];
            float mx = mold;
            #pragma unroll
            for (int c4 = 0; c4 < 16; c4++) mx = fmaxf(mx, Ss[r*SLD + c4*4 + c4o]);
            mx = fmaxf(mx, __shfl_xor_sync(0xffffffffu, mx, 1));
            mx = fmaxf(mx, __shfl_xor_sync(0xffffffffu, mx, 2));
            float sum = 0.f;
            #pragma unroll
            for (int c4 = 0; c4 < 16; c4++) {
                float p = __expf(Ss[r*SLD + c4*4 + c4o] - mx);
                sum += p;
                Ps[r*HLD + c4*4 + c4o] = __float2half_rn(p);
            }
            sum += __shfl_xor_sync(0xffffffffu, sum, 1);
            sum += __shfl_xor_sync(0xffffffffu, sum, 2);
            if (c4o == 0) {
                float alpha = __expf(mold - mx);
                l_s[r] = l_s[r] * alpha + sum;
                m_s[r] = mx;
                a_s[r] = alpha;
            }
        }
        __syncthreads();

        // O = O*alpha + P @ V
        {
            float al0 = a_s[wr + g], al1 = a_s[wr + g + 8];
            #pragma unroll
            for (int ni = 0; ni < 4; ni++) {
                acc[ni][0] *= al0; acc[ni][1] *= al0;
                acc[ni][2] *= al1; acc[ni][3] *= al1;
            }
        }
        #pragma unroll
        for (int kk = 0; kk < 64; kk += 16) {
            uint32_t af[4];
            LDSM4(af[0], af[1], af[2], af[3],
                  psm + (uint32_t)((wr + lrow) * HLD + kk + lko) * 2);
            #pragma unroll
            for (int n2 = 0; n2 < 2; n2++) {
                uint32_t r0, r1, r2, r3;   // trans: rows = kv, cols = hd
                LDSM4T(r0, r1, r2, r3,
                       vsm + (uint32_t)((kk + lrow) * HLD + wc + n2*16 + lko) * 2);
                mma16(acc[n2*2],   af, r0, r1);   // hd cols wc + n2*16 + 0..7
                mma16(acc[n2*2+1], af, r2, r3);   // hd cols wc + n2*16 + 8..15
            }
        }
    }

    // epilogue
    {
        int r0r = wr + g, r1 = r0r + 8;
        float inv0 = 1.f / l_s[r0r], inv1 = 1.f / l_s[r1];
        #pragma unroll
        for (int ni = 0; ni < 4; ni++) {
            int cc = wc + (ni >> 1) * 16 + (ni & 1) * 8 + t * 2;
            *(float2*)&O[headoff + (size_t)(q0 + r0r)*DD + cc] =
                make_float2(acc[ni][0]*inv0, acc[ni][1]*inv0);
            *(float2*)&O[headoff + (size_t)(q0 + r1)*DD + cc] =
                make_float2(acc[ni][2]*inv1, acc[ni][3]*inv1);
        }
    }
}

// ---------------------------------------------------------------------------
extern "C" void kernel_launch(void* const* d_in, const int* in_sizes, int n_in,
                              void* d_out, int out_size)
{
    const float* x     = (const float*)d_in[0];
    const float* freqs = (const float*)d_in[1];
    // d_in[2] = attention_mask (pure causal; handled structurally)
    const float* Wq = (const float*)d_in[3];
    const float* Wk = (const float*)d_in[4];
    const float* Wv = (const float*)d_in[5];
    const float* Wo = (const float*)d_in[6];
    float* out = (float*)d_out;

    float *pQ, *pK, *pV, *pA;
    cudaGetSymbolAddress((void**)&pQ, g_Q);
    cudaGetSymbolAddress((void**)&pK, g_K);
    cudaGetSymbolAddress((void**)&pV, g_V);
    cudaGetSymbolAddress((void**)&pA, g_A);

    // Fused QKV projections (grid.z = 3)
    gemm_f16<<<dim3(DD/BN, ML/BM, 3), 256>>>(x, Wq, Wk, Wv, pQ, pK, pV);

    rope_kernel<<<(ML*(DD/2) + 255)/256, 256>>>(pQ, pK, freqs);

    cudaFuncSetAttribute(flash_f16, cudaFuncAttributeMaxDynamicSharedMemorySize, FL_SMEM_BYTES);
    flash_f16<<<dim3(LL/64, BB*NH), 256, FL_SMEM_BYTES>>>(pQ, pK, pV, pA);

    // Output projection
    gemm_f16<<<dim3(DD/BN, ML/BM, 1), 256>>>(pA, Wo, Wo, Wo, out, out, out);
}

// round 6
// speedup vs baseline: 4.9525x; 1.2344x over previous
#include <cuda_runtime.h>
#include <cuda_fp16.h>
#include <cstdint>

// Problem constants: B=2, L=2048, D=1024, H=16, hd=64
#define BB 2
#define LL 2048
#define DD 1024
#define NH 16
#define HD 64
#define ML (BB*LL)          // 4096 rows

// fp32 scratch (rope inputs)
static __device__ float  g_Q[ML*DD];
static __device__ float  g_K[ML*DD];
// fp16 scratch
static __device__ __half g_xh[ML*DD];
static __device__ __half g_Qh[ML*DD];
static __device__ __half g_Kh[ML*DD];
static __device__ __half g_Vh[ML*DD];
static __device__ __half g_Ah[ML*DD];
static __device__ __half g_Wh[4*DD*DD];

// ---------------------------------------------------------------------------
// helpers
// ---------------------------------------------------------------------------
__device__ __forceinline__ uint32_t smem_u32(const void* p) {
    uint32_t a;
    asm("{ .reg .u64 t; cvta.to.shared.u64 t, %1; cvt.u32.u64 %0, t; }" : "=r"(a) : "l"(p));
    return a;
}

#define CPA16(dst, src) \
    asm volatile("cp.async.cg.shared.global [%0], [%1], 16;" :: "r"(dst), "l"(src))
#define CP_COMMIT() asm volatile("cp.async.commit_group;" ::: "memory")
#define CP_WAIT(n)  asm volatile("cp.async.wait_group %0;" :: "n"(n) : "memory")

#define LDSM4(r0,r1,r2,r3, addr) \
    asm volatile("ldmatrix.sync.aligned.m8n8.x4.shared.b16 {%0,%1,%2,%3}, [%4];" \
        : "=r"(r0),"=r"(r1),"=r"(r2),"=r"(r3) : "r"(addr))

#define LDSM4T(r0,r1,r2,r3, addr) \
    asm volatile("ldmatrix.sync.aligned.m8n8.x4.trans.shared.b16 {%0,%1,%2,%3}, [%4];" \
        : "=r"(r0),"=r"(r1),"=r"(r2),"=r"(r3) : "r"(addr))

__device__ __forceinline__ void mma16(float* c, const uint32_t* a, uint32_t b0, uint32_t b1) {
    asm volatile("mma.sync.aligned.m16n8k16.row.col.f32.f16.f16.f32 "
        "{%0,%1,%2,%3}, {%4,%5,%6,%7}, {%8,%9}, {%0,%1,%2,%3};"
        : "+f"(c[0]), "+f"(c[1]), "+f"(c[2]), "+f"(c[3])
        : "r"(a[0]), "r"(a[1]), "r"(a[2]), "r"(a[3]), "r"(b0), "r"(b1));
}

// ---------------------------------------------------------------------------
// f32 -> f16 conversion
// ---------------------------------------------------------------------------
__global__ void cvt_f16(const float* __restrict__ in, __half* __restrict__ out, int n) {
    int i = (blockIdx.x * blockDim.x + threadIdx.x) * 4;
    if (i >= n) return;
    float4 v = *(const float4*)&in[i];
    __half2 h0 = __floats2half2_rn(v.x, v.y);
    __half2 h1 = __floats2half2_rn(v.z, v.w);
    *(uint2*)&out[i] = make_uint2(*(uint32_t*)&h0, *(uint32_t*)&h1);
}

// ---------------------------------------------------------------------------
// Pipelined FP16 GEMM: C[M,N] = A[M,K] @ W[N,K]^T, fp16 in, 128x128x32 tiles,
// 256 thr (8 warps), warp tile 32x64, cp.async 3-stage pipeline.
// MODE 0: fused QKV (z0->f32 Q, z1->f32 K, z2->f16 V).  MODE 1: f32 out.
// Smem rows: 40 halves (80B) -> conflict-free ldmatrix.
// ---------------------------------------------------------------------------
#define BM 128
#define BN 128
#define BK 32
#define ALD 40
#define STAGE_B 20480          // (128*80)*2 arrays
#define GEMM_SMEM (3*STAGE_B)  // 60 KB

template<int MODE>
__global__ __launch_bounds__(256) void gemm_f16p(
    const __half* __restrict__ A,
    const __half* __restrict__ Wa, const __half* __restrict__ Wb, const __half* __restrict__ Wc,
    float* __restrict__ Cf0, float* __restrict__ Cf1, __half* __restrict__ Ch2,
    float* __restrict__ Cfin)
{
    const int z = blockIdx.z;
    const __half* W = (z == 0) ? Wa : (z == 1) ? Wb : Wc;

    extern __shared__ char smem[];
    const uint32_t s0 = smem_u32(smem);

    const int tid  = threadIdx.x;
    const int lane = tid & 31, warp = tid >> 5;
    const int g = lane >> 2, t = lane & 3;
    const int lrow = lane & 15, lko = (lane >> 4) * 8;
    const int wm = (warp & 3) * 32;
    const int wn = (warp >> 2) * 64;
    const int row0 = blockIdx.y * BM, col0 = blockIdx.x * BN;

    auto load_stage = [&](int st, int k0) {
        uint32_t base = s0 + st * STAGE_B;
        #pragma unroll
        for (int i = 0; i < 2; i++) {
            int cid = tid + i * 256;          // 0..511
            int r = cid >> 2, c4 = cid & 3;
            CPA16(base + r*80 + c4*16,         A + (size_t)(row0 + r) * DD + k0 + c4*8);
            CPA16(base + 10240 + r*80 + c4*16, W + (size_t)(col0 + r) * DD + k0 + c4*8);
        }
        CP_COMMIT();
    };

    float c[2][8][4] = {};

    load_stage(0, 0);
    load_stage(1, BK);

    for (int ch = 0; ch < DD/BK; ch++) {
        CP_WAIT(1);
        __syncthreads();
        if (ch + 2 < DD/BK) load_stage((ch + 2) % 3, (ch + 2) * BK);
        else CP_COMMIT();

        const uint32_t ab = s0 + (ch % 3) * STAGE_B;
        const uint32_t bb = ab + 10240;

        #pragma unroll
        for (int ks = 0; ks < 2; ks++) {
            const int kk = ks * 16;
            uint32_t af[2][4];
            #pragma unroll
            for (int mi = 0; mi < 2; mi++) {
                uint32_t ad = ab + (uint32_t)((wm + mi*16 + lrow) * ALD + kk + lko) * 2;
                LDSM4(af[mi][0], af[mi][1], af[mi][2], af[mi][3], ad);
            }
            #pragma unroll
            for (int n2 = 0; n2 < 4; n2++) {
                uint32_t r0, r1, r2, r3;
                uint32_t bd = bb + (uint32_t)((wn + n2*16 + lrow) * ALD + kk + lko) * 2;
                LDSM4(r0, r1, r2, r3, bd);
                #pragma unroll
                for (int mi = 0; mi < 2; mi++) {
                    mma16(c[mi][n2*2],   af[mi], r0, r2);
                    mma16(c[mi][n2*2+1], af[mi], r1, r3);
                }
            }
        }
        __syncthreads();
    }

    #pragma unroll
    for (int mi = 0; mi < 2; mi++) {
        int r = row0 + wm + mi * 16 + g;
        #pragma unroll
        for (int ni = 0; ni < 8; ni++) {
            int cc = col0 + wn + (ni >> 1) * 16 + (ni & 1) * 8 + t * 2;
            float v0 = c[mi][ni][0], v1 = c[mi][ni][1];
            float v2 = c[mi][ni][2], v3 = c[mi][ni][3];
            if (MODE == 1) {
                *(float2*)&Cfin[(size_t)r * DD + cc]       = make_float2(v0, v1);
                *(float2*)&Cfin[(size_t)(r + 8) * DD + cc] = make_float2(v2, v3);
            } else if (z == 2) {
                __half2 h0 = __floats2half2_rn(v0, v1);
                __half2 h1 = __floats2half2_rn(v2, v3);
                *(__half2*)&Ch2[(size_t)r * DD + cc]       = h0;
                *(__half2*)&Ch2[(size_t)(r + 8) * DD + cc] = h1;
            } else {
                float* C = z ? Cf1 : Cf0;
                *(float2*)&C[(size_t)r * DD + cc]       = make_float2(v0, v1);
                *(float2*)&C[(size_t)(r + 8) * DD + cc] = make_float2(v2, v3);
            }
        }
    }
}

// ---------------------------------------------------------------------------
// RoPE: read f32 Q/K, rotate, write f16 (single half-rounding, matches R5).
// ---------------------------------------------------------------------------
__global__ void rope_h(const float* __restrict__ Q, const float* __restrict__ Kf,
                       __half* __restrict__ Qh, __half* __restrict__ Kh,
                       const float* __restrict__ freqs)
{
    int idx = blockIdx.x * blockDim.x + threadIdx.x;
    if (idx >= ML * (DD/2)) return;
    int row = idx >> 9;
    int p   = idx & 511;
    int l   = row & (LL - 1);
    int pp  = p & (HD/2 - 1);
    float fr = freqs[(l * (HD/2) + pp) * 2 + 0];
    float fi = freqs[(l * (HD/2) + pp) * 2 + 1];
    size_t base = (size_t)row * DD + p * 2;
    float2 q = *(const float2*)&Q[base];
    float2 k = *(const float2*)&Kf[base];
    *(__half2*)&Qh[base] = __floats2half2_rn(q.x*fr - q.y*fi, q.x*fi + q.y*fr);
    *(__half2*)&Kh[base] = __floats2half2_rn(k.x*fr - k.y*fi, k.x*fi + k.y*fr);
}

// ---------------------------------------------------------------------------
// Flash attention (causal), fp16 in/out, cp.async double-buffered K/V.
// Block = (b,h) x 64 q rows. 8 warps: wr=(warp&3)*16, wc=(warp>>2)*32.
// ---------------------------------------------------------------------------
#define HLD 72
#define SLD 68
#define KVH (64*HLD)                  // halves per K or V buffer
#define FL_SMEM_BYTES (6*KVH*2 + 64*SLD*4 + 3*64*4)   // Q,K0,K1,V0,V1,P + Ss + mla

__global__ __launch_bounds__(256) void flash_f16(
    const __half* __restrict__ Q, const __half* __restrict__ K,
    const __half* __restrict__ V, __half* __restrict__ O)
{
    extern __shared__ __half hsm[];
    __half* Qs = hsm;                         // [64][HLD]
    __half* Ps = hsm + 5*KVH;
    float*  Ss = (float*)(hsm + 6*KVH);       // [64][SLD]
    float* m_s = Ss + 64*SLD;
    float* l_s = m_s + 64;
    float* a_s = l_s + 64;

    const int tid = threadIdx.x;
    const int lane = tid & 31, warp = tid >> 5;
    const int g = lane >> 2, t = lane & 3;
    const int lrow = lane & 15, lko = (lane >> 4) * 8;
    const int wr = (warp & 3) * 16;
    const int wc = (warp >> 2) * 32;
    const int b = blockIdx.y >> 4, h = blockIdx.y & 15;
    const int q0 = blockIdx.x * 64;
    const size_t headoff = (size_t)b * LL * DD + (size_t)h * HD;

    const uint32_t qsm = smem_u32(Qs);
    const uint32_t ksm0 = qsm + KVH*2;        // K buffers at halves KVH, 2*KVH
    const uint32_t vsm0 = qsm + 3*KVH*2;
    const uint32_t psm = qsm + 5*KVH*2;

    auto issue_kv = [&](int kt, int buf) {
        const int kv0 = kt * 64;
        uint32_t kb = ksm0 + buf * KVH*2;
        uint32_t vb = vsm0 + buf * KVH*2;
        #pragma unroll
        for (int i = 0; i < 4; i++) {
            int cid = tid + i * 256;          // 0..1023
            int isv = cid >> 9;
            int cc  = cid & 511;
            int r = cc >> 3, c8 = cc & 7;
            const __half* src = (isv ? V : K) + headoff + (size_t)(kv0 + r) * DD + c8*8;
            CPA16((isv ? vb : kb) + r*144 + c8*16, src);
        }
    };

    // group 0: Q tile + kv tile 0
    #pragma unroll
    for (int i = 0; i < 2; i++) {
        int cid = tid + i * 256;
        int r = cid >> 3, c8 = cid & 7;
        CPA16(qsm + r*144 + c8*16, Q + headoff + (size_t)(q0 + r) * DD + c8*8);
    }
    issue_kv(0, 0);
    CP_COMMIT();
    const int ntiles = blockIdx.x + 1;
    if (ntiles > 1) issue_kv(1, 1);
    CP_COMMIT();

    if (tid < 64) { m_s[tid] = -1e30f; l_s[tid] = 0.f; }

    float acc[4][4] = {};

    for (int kt = 0; kt < ntiles; kt++) {
        const int kv0 = kt * 64;
        const uint32_t kb = ksm0 + (kt & 1) * KVH*2;
        const uint32_t vb = vsm0 + (kt & 1) * KVH*2;
        CP_WAIT(1);
        __syncthreads();

        // S = Q @ K^T
        float sfrag[4][4] = {};
        #pragma unroll
        for (int kk = 0; kk < HD; kk += 16) {
            uint32_t af[4];
            LDSM4(af[0], af[1], af[2], af[3],
                  qsm + (uint32_t)((wr + lrow) * HLD + kk + lko) * 2);
            #pragma unroll
            for (int n2 = 0; n2 < 2; n2++) {
                uint32_t r0, r1, r2, r3;
                LDSM4(r0, r1, r2, r3,
                      kb + (uint32_t)((wc + n2*16 + lrow) * HLD + kk + lko) * 2);
                mma16(sfrag[n2*2],   af, r0, r2);
                mma16(sfrag[n2*2+1], af, r1, r3);
            }
        }
        const bool diag = (kt == ntiles - 1);
        #pragma unroll
        for (int ni = 0; ni < 4; ni++) {
            int r0r = wr + g, r1 = r0r + 8;
            int cc = wc + (ni >> 1) * 16 + (ni & 1) * 8 + t * 2;
            float v0 = sfrag[ni][0]*0.125f, v1 = sfrag[ni][1]*0.125f;
            float v2 = sfrag[ni][2]*0.125f, v3 = sfrag[ni][3]*0.125f;
            if (diag) {
                int gr0 = q0 + r0r, gr1 = q0 + r1, gc = kv0 + cc;
                if (gc     > gr0) v0 = -1e30f;
                if (gc + 1 > gr0) v1 = -1e30f;
                if (gc     > gr1) v2 = -1e30f;
                if (gc + 1 > gr1) v3 = -1e30f;
            }
            *(float2*)&Ss[r0r*SLD + cc] = make_float2(v0, v1);
            *(float2*)&Ss[r1*SLD + cc]  = make_float2(v2, v3);
        }
        __syncthreads();

        // online softmax: 4 threads per row; writes P as fp16
        {
            int r = tid >> 2, c4o = tid & 3;
            float mold = m_s[r];
            float mx = mold;
            #pragma unroll
            for (int c4 = 0; c4 < 16; c4++) mx = fmaxf(mx, Ss[r*SLD + c4*4 + c4o]);
            mx = fmaxf(mx, __shfl_xor_sync(0xffffffffu, mx, 1));
            mx = fmaxf(mx, __shfl_xor_sync(0xffffffffu, mx, 2));
            float sum = 0.f;
            #pragma unroll
            for (int c4 = 0; c4 < 16; c4++) {
                float p = __expf(Ss[r*SLD + c4*4 + c4o] - mx);
                sum += p;
                Ps[r*HLD + c4*4 + c4o] = __float2half_rn(p);
            }
            sum += __shfl_xor_sync(0xffffffffu, sum, 1);
            sum += __shfl_xor_sync(0xffffffffu, sum, 2);
            if (c4o == 0) {
                float alpha = __expf(mold - mx);
                l_s[r] = l_s[r] * alpha + sum;
                m_s[r] = mx;
                a_s[r] = alpha;
            }
        }
        __syncthreads();

        // O = O*alpha + P @ V
        {
            float al0 = a_s[wr + g], al1 = a_s[wr + g + 8];
            #pragma unroll
            for (int ni = 0; ni < 4; ni++) {
                acc[ni][0] *= al0; acc[ni][1] *= al0;
                acc[ni][2] *= al1; acc[ni][3] *= al1;
            }
        }
        #pragma unroll
        for (int kk = 0; kk < 64; kk += 16) {
            uint32_t af[4];
            LDSM4(af[0], af[1], af[2], af[3],
                  psm + (uint32_t)((wr + lrow) * HLD + kk + lko) * 2);
            #pragma unroll
            for (int n2 = 0; n2 < 2; n2++) {
                uint32_t r0, r1, r2, r3;
                LDSM4T(r0, r1, r2, r3,
                       vb + (uint32_t)((kk + lrow) * HLD + wc + n2*16 + lko) * 2);
                mma16(acc[n2*2],   af, r0, r1);
                mma16(acc[n2*2+1], af, r2, r3);
            }
        }
        __syncthreads();
        if (kt + 2 < ntiles) issue_kv(kt + 2, kt & 1);
        CP_COMMIT();
    }

    // epilogue (fp16 out)
    {
        int r0r = wr + g, r1 = r0r + 8;
        float inv0 = 1.f / l_s[r0r], inv1 = 1.f / l_s[r1];
        #pragma unroll
        for (int ni = 0; ni < 4; ni++) {
            int cc = wc + (ni >> 1) * 16 + (ni & 1) * 8 + t * 2;
            *(__half2*)&O[headoff + (size_t)(q0 + r0r)*DD + cc] =
                __floats2half2_rn(acc[ni][0]*inv0, acc[ni][1]*inv0);
            *(__half2*)&O[headoff + (size_t)(q0 + r1)*DD + cc] =
                __floats2half2_rn(acc[ni][2]*inv1, acc[ni][3]*inv1);
        }
    }
}

// ---------------------------------------------------------------------------
extern "C" void kernel_launch(void* const* d_in, const int* in_sizes, int n_in,
                              void* d_out, int out_size)
{
    const float* x     = (const float*)d_in[0];
    const float* freqs = (const float*)d_in[1];
    // d_in[2] = attention_mask (pure causal; handled structurally)
    const float* Wq = (const float*)d_in[3];
    const float* Wk = (const float*)d_in[4];
    const float* Wv = (const float*)d_in[5];
    const float* Wo = (const float*)d_in[6];
    float* out = (float*)d_out;

    float *pQ, *pK;
    __half *pxh, *pQh, *pKh, *pVh, *pAh, *pWh;
    cudaGetSymbolAddress((void**)&pQ,  g_Q);
    cudaGetSymbolAddress((void**)&pK,  g_K);
    cudaGetSymbolAddress((void**)&pxh, g_xh);
    cudaGetSymbolAddress((void**)&pQh, g_Qh);
    cudaGetSymbolAddress((void**)&pKh, g_Kh);
    cudaGetSymbolAddress((void**)&pVh, g_Vh);
    cudaGetSymbolAddress((void**)&pAh, g_Ah);
    cudaGetSymbolAddress((void**)&pWh, g_Wh);

    // f32 -> f16 conversions
    cvt_f16<<<(ML*DD/4 + 255)/256, 256>>>(x,  pxh, ML*DD);
    cvt_f16<<<(DD*DD/4 + 255)/256, 256>>>(Wq, pWh + 0*DD*DD, DD*DD);
    cvt_f16<<<(DD*DD/4 + 255)/256, 256>>>(Wk, pWh + 1*DD*DD, DD*DD);
    cvt_f16<<<(DD*DD/4 + 255)/256, 256>>>(Wv, pWh + 2*DD*DD, DD*DD);
    cvt_f16<<<(DD*DD/4 + 255)/256, 256>>>(Wo, pWh + 3*DD*DD, DD*DD);

    cudaFuncSetAttribute(gemm_f16p<0>, cudaFuncAttributeMaxDynamicSharedMemorySize, GEMM_SMEM);
    cudaFuncSetAttribute(gemm_f16p<1>, cudaFuncAttributeMaxDynamicSharedMemorySize, GEMM_SMEM);

    // Fused QKV projections: z0 -> f32 Q, z1 -> f32 K, z2 -> f16 V
    gemm_f16p<0><<<dim3(DD/BN, ML/BM, 3), 256, GEMM_SMEM>>>(
        pxh, pWh, pWh + DD*DD, pWh + 2*DD*DD, pQ, pK, pVh, nullptr);

    rope_h<<<(ML*(DD/2) + 255)/256, 256>>>(pQ, pK, pQh, pKh, freqs);

    cudaFuncSetAttribute(flash_f16, cudaFuncAttributeMaxDynamicSharedMemorySize, FL_SMEM_BYTES);
    flash_f16<<<dim3(LL/64, BB*NH), 256, FL_SMEM_BYTES>>>(pQh, pKh, pVh, pAh);

    // Output projection: f16 A @ Wo^T -> f32 out
    gemm_f16p<1><<<dim3(DD/BN, ML/BM, 1), 256, GEMM_SMEM>>>(
        pAh, pWh + 3*DD*DD, nullptr, nullptr, nullptr, nullptr, nullptr, out);
}